// round 12
// baseline (speedup 1.0000x reference)
#include <cuda_runtime.h>
typedef unsigned int u32;

#define HH 4096
#define ROWF 12288          // floats per image row
#define TPB 384             // one thread per (col, chan)
#define RS 408              // floats per staged row (128+8 halo cols, f4-aligned)
#define BUFF 3264           // floats per 8-row stage buffer
#define BUF8B 13056         // bytes per 8-row stage buffer
#define SHIF 9792           // smem float offset of shI (3 stage bufs)
#define SMEMB 63744         // 3*13056 + 2*8*384*4

// horizontal taps: radius-1, renormalized to unit applied mass
#define KH0 0.78698593f
#define KH1 0.10650699f
// vertical taps: radius-2, reference-normalized
#define K0f 0.78657070f
#define K1f 0.10645078f
#define K2f 2.63866e-4f
#define DECAYf 0.60653065971263342f
#define OMDf   0.39346934028736658f
#define INV3f  0.33333322222f        // 1/(3 + 1e-6)

__global__ __launch_bounds__(TPB, 2)
void chem_kernel(const float* __restrict__ D, const float* __restrict__ Cm,
                 float* __restrict__ out)
{
    extern __shared__ float smem[];
    float* stage = smem;                 // 3 bufs x 8 rows x 408
    float* shIb  = smem + SHIF;          // 2 parities x 8 rows x 384

    const int tid = threadIdx.x;
    const int c   = tid % 3;
    const int wb_ = tid - c;
    const int w0  = blockIdx.x << 7;     // 32 strips of 128 cols
    const int h0  = blockIdx.y << 9;     // 8 chunks of 512 rows

    const float cc0 = __ldg(Cm + 0 + c);
    const float cc1 = __ldg(Cm + 3 + c);
    const float cc2 = __ldg(Cm + 6 + c);

    // cp.async loader: 816 float4 vectors per 8-row batch -> 3 mappings/thread
    const int  ja = tid / 102,          va = tid - ja * 102;
    const int  tb = tid + 384;
    const int  jb = tb / 102,           vb = tb - jb * 102;
    const bool hc = tid < 48;
    const int  vc = tid + 54;                         // jc = 7
    const long base3 = (long)(w0 - 4) * 3;
    const long ga = base3 + 4 * va;  const bool coka = (ga >= 0) && (ga + 4 <= ROWF);
    const long gb = base3 + 4 * vb;  const bool cokb = (gb >= 0) && (gb + 4 <= ROWF);
    const long gc = base3 + 4 * vc;  const bool cokc = hc && (gc >= 0) && (gc + 4 <= ROWF);

    const u32 sb0 = (u32)__cvta_generic_to_shared(smem);
    const u32 saA = sb0 + (u32)((ja * RS + 4 * va) * 4);
    const u32 saB = sb0 + (u32)((jb * RS + 4 * vb) * 4);
    const u32 saC = sb0 + (u32)((7  * RS + 4 * vc) * 4);

    float hb[8] = {0,0,0,0,0,0,0,0};   // horizontal-blur ring
    float dr[4] = {0,0,0,0};           // raw density ring (lag 2)
    float sr[4] = {0,0,0,0};           // soft-cloud ring (lag 2)
    float ds[8];                       // density stash (consumed before refill)
    float siir = 0.f;

    int rb = h0 - 30;                  // 68 batches of 8 rows; shI from batch 4
    float* opm = out + (long)h0 * ROWF + w0 * 3 + tid;   // MIX write cursor

#define CPA(SA, GOK, J, V, GOFF, RB, SB) { \
    const int  row = (RB) + (J); \
    const int  sz  = ((GOK) && row >= 0 && row < HH) ? 16 : 0; \
    const float* gp = sz ? (D + (long)row * ROWF + (GOFF)) : D; \
    asm volatile("cp.async.cg.shared.global [%0], [%1], 16, %2;\n" \
                 :: "r"((SA) + (u32)(SB) * BUF8B), "l"(gp), "r"(sz) : "memory"); }

#define ISSUE(RB, SB) { \
    CPA(saA, coka, ja, va, ga, RB, SB) \
    CPA(saB, cokb, jb, vb, gb, RB, SB) \
    if (hc) CPA(saC, cokc, 7, vc, gc, RB, SB) \
    asm volatile("cp.async.commit_group;\n" ::: "memory"); }

// warm row: horizontal blur + IIR + rings only
#define ROWW(S) { \
    const float* bp = stgf + (S) * RS; \
    const float xm1 = bp[tid+9], x0 = bp[tid+12], xp1 = bp[tid+15]; \
    siir = fmaf(DECAYf, siir, x0); \
    hb[(S)&7] = fmaf(xm1 + xp1, KH1, x0 * KH0); \
    dr[(S)&3] = x0; \
    sr[(S)&3] = OMDf * siir; }

// emit row: + vertical blur (radius 2), mask blend, shI/ds stash (ro = r-2)
#define ROWE(S, PH) { \
    const float* bp = stgf + (S) * RS; \
    const float xm1 = bp[tid+9], x0 = bp[tid+12], xp1 = bp[tid+15]; \
    siir = fmaf(DECAYf, siir, x0); \
    hb[(S)&7] = fmaf(xm1 + xp1, KH1, x0 * KH0); \
    float vb_ = hb[((S)+6)&7] * K0f; \
    vb_ = fmaf(hb[((S)+5)&7] + hb[((S)+7)&7], K1f, vb_); \
    vb_ = fmaf(hb[((S)+4)&7] + hb[(S)&7],     K2f, vb_); \
    const float d_o = dr[((S)+2)&3]; \
    const float s_o = sr[((S)+2)&3]; \
    ds[S] = d_o; \
    shIb[(PH)*3072 + (S)*384 + tid] = s_o + (d_o * INV3f) * (vb_ - s_o); \
    dr[(S)&3] = x0; \
    sr[(S)&3] = OMDf * siir; }

#define MIX1(PB, J) { \
    const float* sI = shIb + (PB)*3072 + (J)*384; \
    const float i0 = sI[wb_], i1 = sI[wb_+1], i2 = sI[wb_+2]; \
    const float inh = cc0*i0 + cc1*i1 + cc2*i2; \
    const float arg = (ds[J] - inh) * INV3f; \
    float t; asm("tanh.approx.f32 %0, %1;" : "=f"(t) : "f"(arg)); \
    opm[(J) * (long)ROWF] = 3.0f * t; }

#define MIXB(PB) { MIX1(PB,0) MIX1(PB,1) MIX1(PB,2) MIX1(PB,3) \
                   MIX1(PB,4) MIX1(PB,5) MIX1(PB,6) MIX1(PB,7) \
                   opm += 8 * (long)ROWF; }

#define CPWAIT(N) asm volatile("cp.async.wait_group " #N ";\n" ::: "memory")

#define BWARM(SB, TB) { \
    CPWAIT(1); __syncthreads(); \
    ISSUE(rb + 16, TB) \
    const float* stgf = stage + (SB) * BUFF; \
    ROWW(0) ROWW(1) ROWW(2) ROWW(3) ROWW(4) ROWW(5) ROWW(6) ROWW(7) \
    rb += 8; }

// MIX consumes ds[] of previous super BEFORE ROWE refills it (same-thread order)
#define BEMIT(SB, TB, PH, DOMIX, DOISS, WN) { \
    CPWAIT(WN); __syncthreads(); \
    if (DOISS) ISSUE(rb + 16, TB) \
    if (DOMIX) { MIXB((PH)^1) } \
    const float* stgf = stage + (SB) * BUFF; \
    ROWE(0,PH) ROWE(1,PH) ROWE(2,PH) ROWE(3,PH) \
    ROWE(4,PH) ROWE(5,PH) ROWE(6,PH) ROWE(7,PH) \
    rb += 8; }

    // prologue: batches 0,1 in flight
    ISSUE(rb,     0)
    ISSUE(rb + 8, 1)

    // warm-up: batches 0..3 (rows h0-30 .. h0+1)
    BWARM(0,2) BWARM(1,0) BWARM(2,1) BWARM(0,2)

    // k=4: first shI batch (ro = h0..h0+7), no MIX yet
    BEMIT(1,0, 0, 0,1,1)

    // k=5..64: steady state, period-6 (buf mod 3 x parity mod 2)
#pragma unroll 1
    for (int p = 0; p < 10; ++p) {
        BEMIT(2,1, 1, 1,1,1) BEMIT(0,2, 0, 1,1,1) BEMIT(1,0, 1, 1,1,1)
        BEMIT(2,1, 0, 1,1,1) BEMIT(0,2, 1, 1,1,1) BEMIT(1,0, 0, 1,1,1)
    }

    // k=65 (last ISSUE: batch 67), k=66, k=67
    BEMIT(2,1, 1, 1,1,1)
    BEMIT(0,2, 0, 1,0,1)
    BEMIT(1,0, 1, 1,0,0)

    // epilogue: store batch 67's rows (h0+504 .. h0+511)
    __syncthreads();
    MIXB(1)

#undef BWARM
#undef BEMIT
#undef CPWAIT
#undef MIXB
#undef MIX1
#undef ROWE
#undef ROWW
#undef ISSUE
#undef CPA
}

extern "C" void kernel_launch(void* const* d_in, const int* in_sizes, int n_in,
                              void* d_out, int out_size)
{
    const float* D   = (const float*)d_in[0];   // (4096, 4096, 3) f32
    const float* Cm  = (const float*)d_in[1];   // (3, 3) f32
    float*       out = (float*)d_out;           // (4096, 4096, 3) f32
    cudaFuncSetAttribute(chem_kernel, cudaFuncAttributeMaxDynamicSharedMemorySize, SMEMB);
    dim3 grid(32, 8);                           // 256 blocks, 512-row chunks
    chem_kernel<<<grid, TPB, SMEMB>>>(D, Cm, out);
}